// round 4
// baseline (speedup 1.0000x reference)
#include <cuda_runtime.h>
#include <math.h>
#include <stdint.h>

#define MAXN 100000
#define MAXE 1600000

// ---------------- scratch (static device arrays; no allocation) ----------------
__device__ float g_dinv[MAXN];            // deg accum, then rsqrt(deg)
__device__ int   g_cnt[MAXN];
__device__ int   g_cur[MAXN];
__device__ int   g_offs[MAXN + 1];
__device__ int2  g_edge[MAXE];            // {src, bitcast(norm)} CSR payload
__device__ float g_A2[(size_t)MAXN * 192];// [XA(128) | h(64)] per node
__device__ float g_P[(size_t)MAXN * 192]; // [Zpre' | Rpre' | Ht_partial]
__device__ float g_c[192];
// W2 split into tf32 hi/lo: [k(192) x j(192)], row-major
__device__ float g_Bhi[192 * 192];
__device__ float g_Blo[192 * 192];

// ---------------- PTX helpers ----------------
__device__ __forceinline__ float tf32_rnd(float v) {
    uint32_t r;
    asm("cvt.rna.tf32.f32 %0, %1;" : "=r"(r) : "f"(v));
    return __uint_as_float(r);
}
__device__ __forceinline__ void mma_tf32(float* d, const uint32_t* a,
                                         uint32_t b0, uint32_t b1) {
    asm volatile(
        "mma.sync.aligned.m16n8k8.row.col.f32.tf32.tf32.f32 "
        "{%0,%1,%2,%3}, {%4,%5,%6,%7}, {%8,%9}, {%0,%1,%2,%3};"
        : "+f"(d[0]), "+f"(d[1]), "+f"(d[2]), "+f"(d[3])
        : "r"(a[0]), "r"(a[1]), "r"(a[2]), "r"(a[3]), "r"(b0), "r"(b1));
}

// ---------------- setup: init + W2 fold (tf32 hi/lo) + bias fold ----------------
__global__ void k_setup(const float* __restrict__ Wz, const float* __restrict__ Wr,
                        const float* __restrict__ Wh, const float* __restrict__ Lz,
                        const float* __restrict__ Lr, const float* __restrict__ Lh,
                        const float* __restrict__ bz, const float* __restrict__ br,
                        const float* __restrict__ bh, const float* __restrict__ bLz,
                        const float* __restrict__ bLr, const float* __restrict__ bLh,
                        int n) {
    int i = blockIdx.x * blockDim.x + threadIdx.x;
    if (i < n) { g_dinv[i] = 1.0f; g_cnt[i] = 0; g_cur[i] = 0; }
    if (i < 192 * 192) {
        int k = i / 192, j = i % 192;   // k: inner dim (A2 cols), j: output col
        float val;
        if (k < 128) {
            int g = j >> 6, jj = j & 63;
            const float* W = (g == 0) ? Wz : ((g == 1) ? Wr : Wh);
            const float* L = (g == 0) ? Lz : ((g == 1) ? Lr : Lh);
            float s = 0.f;
            #pragma unroll 8
            for (int m = 0; m < 64; m++) s = fmaf(W[k * 64 + m], L[m * 64 + jj], s);
            val = s;
        } else {
            int kk = k - 128;
            if (j < 64)       val = Lz[(64 + kk) * 64 + j];
            else if (j < 128) val = Lr[(64 + kk) * 64 + (j - 64)];
            else              val = 0.f;       // (h*R) @ Lh_bot handled in finalize
        }
        float hi = tf32_rnd(val);
        g_Bhi[i] = hi;
        g_Blo[i] = tf32_rnd(val - hi);
    }
    if (i < 192) {
        int g = i >> 6, jj = i & 63;
        const float* b  = (g == 0) ? bz  : ((g == 1) ? br  : bh);
        const float* L  = (g == 0) ? Lz  : ((g == 1) ? Lr  : Lh);
        const float* bL = (g == 0) ? bLz : ((g == 1) ? bLr : bLh);
        float s = bL[jj];
        #pragma unroll 8
        for (int m = 0; m < 64; m++) s = fmaf(b[m], L[m * 64 + jj], s);
        g_c[i] = s;
    }
}

// ---------------- degree histogram ----------------
__global__ void k_hist(const int* __restrict__ ei, const float* __restrict__ ew, int E) {
    int e = blockIdx.x * blockDim.x + threadIdx.x;
    if (e < E) {
        int c = ei[E + e];
        atomicAdd(&g_dinv[c], ew[e]);
        atomicAdd(&g_cnt[c], 1);
    }
}

// ---------------- dinv + exclusive scan, single block ----------------
__global__ void k_scan1(int n, int E) {
    int tid = threadIdx.x;
    for (int i = tid; i < n; i += 1024) g_dinv[i] = rsqrtf(g_dinv[i]);  // deg>=1 (self-loop)

    __shared__ int s[1024];
    int per = (n + 1023) >> 10;
    int start = tid * per;
    int end = start + per; if (end > n) end = n; if (start > n) start = n;
    int sum = 0;
    for (int i = start; i < end; i++) sum += g_cnt[i];
    s[tid] = sum; __syncthreads();
    int v = sum;
    for (int d = 1; d < 1024; d <<= 1) {
        int t = (tid >= d) ? s[tid - d] : 0;
        __syncthreads();
        s[tid] += t;
        __syncthreads();
    }
    int pre = s[tid] - v;
    for (int i = start; i < end; i++) { g_offs[i] = pre; pre += g_cnt[i]; }
    if (tid == 0) g_offs[n] = E;
}

// ---------------- CSR fill ----------------
__global__ void k_fill(const int* __restrict__ ei, const float* __restrict__ ew, int E) {
    int e = blockIdx.x * blockDim.x + threadIdx.x;
    if (e < E) {
        int r = ei[e];
        int c = ei[E + e];
        float nrm = g_dinv[r] * ew[e] * g_dinv[c];
        int pos = g_offs[c] + atomicAdd(&g_cur[c], 1);
        g_edge[pos] = make_int2(r, __float_as_int(nrm));
    }
}

// ---------------- aggregation + h copy: A2 = [XA | h] ----------------
__global__ __launch_bounds__(256) void k_agg(const float* __restrict__ x,
                                             const float* __restrict__ h, int n) {
    int warp = threadIdx.x >> 5, lane = threadIdx.x & 31;
    int node = blockIdx.x * 8 + warp;
    if (node >= n) return;
    const float4* xv = (const float4*)x;
    float di = g_dinv[node];
    float s = di * di;
    float4 a = xv[(size_t)node * 32 + lane];
    float4 acc = make_float4(s * a.x, s * a.y, s * a.z, s * a.w);
    int j = g_offs[node], j1 = g_offs[node + 1];
    for (; j + 1 < j1; j += 2) {
        int2 e0 = g_edge[j], e1 = g_edge[j + 1];
        float4 v0 = xv[(size_t)e0.x * 32 + lane];
        float4 v1 = xv[(size_t)e1.x * 32 + lane];
        float w0 = __int_as_float(e0.y), w1 = __int_as_float(e1.y);
        acc.x = fmaf(w0, v0.x, acc.x); acc.y = fmaf(w0, v0.y, acc.y);
        acc.z = fmaf(w0, v0.z, acc.z); acc.w = fmaf(w0, v0.w, acc.w);
        acc.x = fmaf(w1, v1.x, acc.x); acc.y = fmaf(w1, v1.y, acc.y);
        acc.z = fmaf(w1, v1.z, acc.z); acc.w = fmaf(w1, v1.w, acc.w);
    }
    if (j < j1) {
        int2 e0 = g_edge[j];
        float4 v0 = xv[(size_t)e0.x * 32 + lane];
        float w0 = __int_as_float(e0.y);
        acc.x = fmaf(w0, v0.x, acc.x); acc.y = fmaf(w0, v0.y, acc.y);
        acc.z = fmaf(w0, v0.z, acc.z); acc.w = fmaf(w0, v0.w, acc.w);
    }
    ((float4*)g_A2)[(size_t)node * 48 + lane] = acc;
    if (lane < 16)
        ((float4*)g_A2)[(size_t)node * 48 + 32 + lane] =
            ((const float4*)h)[(size_t)node * 16 + lane];
}

// ---------------- 3xTF32 mma.sync GEMM: P[N,192] = A2[N,192] @ W2[192,192] ----------------
// CTA: M=64 rows. 8 warps = 4 row-strips(16) x 2 n-halves(96).
// K processed in 8 chunks of 24 (3 k-steps of 8). B staged hi/lo in smem, pad 200.
#define BPAD 200

__global__ __launch_bounds__(256) void k_gemm_mma(int n) {
    __shared__ float sBhi[24 * BPAD];
    __shared__ float sBlo[24 * BPAD];

    int tid = threadIdx.x;
    int wid = tid >> 5, lane = tid & 31;
    int strip = wid >> 1;            // 0..3
    int half = wid & 1;              // 0..1
    int gid = lane >> 2;             // groupID 0..7
    int tig = lane & 3;              // threadInGroup 0..3

    int rowBase = blockIdx.x * 64;
    int row0 = rowBase + strip * 16 + gid;
    int row1 = row0 + 8;
    bool ok0 = row0 < n, ok1 = row1 < n;

    float d[12][4];
    #pragma unroll
    for (int nt = 0; nt < 12; nt++)
        #pragma unroll
        for (int q = 0; q < 4; q++) d[nt][q] = 0.f;

    const float* A0 = g_A2 + (size_t)row0 * 192;
    const float* A1 = g_A2 + (size_t)row1 * 192;

    for (int c = 0; c < 8; c++) {
        // stage B chunk: rows c*24 .. c*24+23 of g_Bhi/g_Blo (192 cols -> pad 200)
        {
            const float4* srch = (const float4*)(g_Bhi + c * 24 * 192);
            const float4* srcl = (const float4*)(g_Blo + c * 24 * 192);
            float4* dsth = (float4*)sBhi;
            float4* dstl = (float4*)sBlo;
            #pragma unroll
            for (int t = tid; t < 24 * 48; t += 256) {
                int k = t / 48, j4 = t % 48;
                dsth[k * (BPAD / 4) + j4] = srch[t];
                dstl[k * (BPAD / 4) + j4] = srcl[t];
            }
        }
        __syncthreads();

        #pragma unroll
        for (int ks = 0; ks < 3; ks++) {
            int kb = c * 24 + ks * 8;
            // A fragment (hi and lo)
            float v0 = ok0 ? A0[kb + tig]     : 0.f;
            float v1 = ok1 ? A1[kb + tig]     : 0.f;
            float v2 = ok0 ? A0[kb + tig + 4] : 0.f;
            float v3 = ok1 ? A1[kb + tig + 4] : 0.f;
            float h0 = tf32_rnd(v0), h1 = tf32_rnd(v1);
            float h2 = tf32_rnd(v2), h3 = tf32_rnd(v3);
            uint32_t ahi[4] = { __float_as_uint(h0), __float_as_uint(h1),
                                __float_as_uint(h2), __float_as_uint(h3) };
            uint32_t alo[4] = { __float_as_uint(tf32_rnd(v0 - h0)),
                                __float_as_uint(tf32_rnd(v1 - h1)),
                                __float_as_uint(tf32_rnd(v2 - h2)),
                                __float_as_uint(tf32_rnd(v3 - h3)) };
            int kr0 = (ks * 8 + tig) * BPAD;
            int kr1 = (ks * 8 + tig + 4) * BPAD;
            #pragma unroll
            for (int nt = 0; nt < 12; nt++) {
                int nn = half * 96 + nt * 8 + gid;
                uint32_t b0h = __float_as_uint(sBhi[kr0 + nn]);
                uint32_t b1h = __float_as_uint(sBhi[kr1 + nn]);
                uint32_t b0l = __float_as_uint(sBlo[kr0 + nn]);
                uint32_t b1l = __float_as_uint(sBlo[kr1 + nn]);
                mma_tf32(d[nt], ahi, b0h, b1h);
                mma_tf32(d[nt], ahi, b0l, b1l);
                mma_tf32(d[nt], alo, b0h, b1h);
            }
        }
        __syncthreads();
    }

    // epilogue: d[nt][0..1] -> (row0, col..col+1), d[nt][2..3] -> (row1, ...)
    #pragma unroll
    for (int nt = 0; nt < 12; nt++) {
        int col = half * 96 + nt * 8 + tig * 2;
        if (ok0) *(float2*)(g_P + (size_t)row0 * 192 + col) = make_float2(d[nt][0], d[nt][1]);
        if (ok1) *(float2*)(g_P + (size_t)row1 * 192 + col) = make_float2(d[nt][2], d[nt][3]);
    }
}

// ---------------- finalize: gates, (h*R)@Lh_bot, GRU blend, head ----------------
__device__ __forceinline__ float sigf(float v) { return 1.f / (1.f + __expf(-v)); }

__global__ __launch_bounds__(256) void k_final(const float* __restrict__ h,
                                               const float* __restrict__ Lh,
                                               const float* __restrict__ Wo,
                                               const float* __restrict__ bo,
                                               float* __restrict__ out, int n) {
    __shared__ float Lhb[64][65];
    __shared__ float sWo[64];
    __shared__ float sc[192];
    int tid = threadIdx.x;
    for (int i = tid; i < 4096; i += 256) {
        int k = i >> 6, j = i & 63;
        Lhb[k][j] = Lh[(64 + k) * 64 + j];
    }
    if (tid < 64) sWo[tid] = Wo[tid];
    if (tid < 192) sc[tid] = g_c[tid];
    __syncthreads();

    int warp = tid >> 5, lane = tid & 31;
    int node = blockIdx.x * 8 + warp;
    if (node >= n) return;

    const float* p = g_P + (size_t)node * 192;
    float z0 = sigf(p[lane]       + sc[lane]);
    float z1 = sigf(p[lane + 32]  + sc[lane + 32]);
    float r0 = sigf(p[lane + 64]  + sc[lane + 64]);
    float r1 = sigf(p[lane + 96]  + sc[lane + 96]);
    float q0 =      p[lane + 128] + sc[lane + 128];
    float q1 =      p[lane + 160] + sc[lane + 160];

    float h0 = h[(size_t)node * 64 + lane];
    float h1 = h[(size_t)node * 64 + lane + 32];
    float v0 = h0 * r0, v1 = h1 * r1;

    float acc0 = q0, acc1 = q1;
    #pragma unroll
    for (int k = 0; k < 32; k++) {
        float vk = __shfl_sync(0xffffffffu, v0, k);
        acc0 = fmaf(vk, Lhb[k][lane], acc0);
        acc1 = fmaf(vk, Lhb[k][lane + 32], acc1);
    }
    #pragma unroll
    for (int k = 0; k < 32; k++) {
        float vk = __shfl_sync(0xffffffffu, v1, k);
        acc0 = fmaf(vk, Lhb[k + 32][lane], acc0);
        acc1 = fmaf(vk, Lhb[k + 32][lane + 32], acc1);
    }
    float t0 = tanhf(acc0), t1 = tanhf(acc1);
    float hn0 = z0 * h0 + (1.f - z0) * t0;
    float hn1 = z1 * h1 + (1.f - z1) * t1;

    out[n + (size_t)node * 64 + lane]      = hn0;
    out[n + (size_t)node * 64 + lane + 32] = hn1;

    float dot = hn0 * sWo[lane] + hn1 * sWo[lane + 32];
    #pragma unroll
    for (int o = 16; o; o >>= 1) dot += __shfl_down_sync(0xffffffffu, dot, o);
    if (lane == 0) out[node] = dot + bo[0];
}

// ---------------- launcher ----------------
extern "C" void kernel_launch(void* const* d_in, const int* in_sizes, int n_in,
                              void* d_out, int out_size) {
    const float* x   = (const float*)d_in[0];
    const int*   ei  = (const int*)  d_in[1];
    const float* ew  = (const float*)d_in[2];
    const float* h   = (const float*)d_in[3];
    const float* Wz  = (const float*)d_in[4];
    const float* bz  = (const float*)d_in[5];
    const float* Wr  = (const float*)d_in[6];
    const float* br  = (const float*)d_in[7];
    const float* Wh  = (const float*)d_in[8];
    const float* bh  = (const float*)d_in[9];
    const float* Lz  = (const float*)d_in[10];
    const float* bLz = (const float*)d_in[11];
    const float* Lr  = (const float*)d_in[12];
    const float* bLr = (const float*)d_in[13];
    const float* Lh  = (const float*)d_in[14];
    const float* bLh = (const float*)d_in[15];
    const float* Wo  = (const float*)d_in[16];
    const float* bo  = (const float*)d_in[17];
    float* out = (float*)d_out;

    int N = in_sizes[0] / 128;
    int E = in_sizes[2];
    int setup_elems = (N > 192 * 192) ? N : 192 * 192;

    k_setup<<<(setup_elems + 255) / 256, 256>>>(Wz, Wr, Wh, Lz, Lr, Lh,
                                                bz, br, bh, bLz, bLr, bLh, N);
    k_hist<<<(E + 255) / 256, 256>>>(ei, ew, E);
    k_scan1<<<1, 1024>>>(N, E);
    k_fill<<<(E + 255) / 256, 256>>>(ei, ew, E);
    k_agg<<<(N + 7) / 8, 256>>>(x, h, N);
    k_gemm_mma<<<(N + 63) / 64, 256>>>(N);
    k_final<<<(N + 7) / 8, 256>>>(h, Lh, Wo, bo, out, N);
}

// round 5
// speedup vs baseline: 1.4875x; 1.4875x over previous
#include <cuda_runtime.h>
#include <math.h>
#include <stdint.h>

#define MAXN 100000
#define MAXE 1600000
#define NPAD (MAXN + 128)

// ---------------- scratch (static device arrays; no allocation) ----------------
__device__ float g_dinv[MAXN];            // deg accum, then rsqrt(deg)
__device__ int   g_cnt[MAXN];
__device__ int   g_cur[MAXN];
__device__ int   g_offs[MAXN + 1];
__device__ int2  g_edge[MAXE];            // {src, bitcast(norm)} CSR payload
__device__ float g_Ahi[(size_t)NPAD * 192]; // tf32-hi of [XA(128) | h(64)]
__device__ float g_Alo[(size_t)NPAD * 192]; // tf32-lo remainder
__device__ float g_P[(size_t)NPAD * 192];   // [Zpre' | Rpre' | Ht_partial]
__device__ float g_c[192];
// W2 split into tf32 hi/lo: [k(192) x j(192)], row-major
__device__ float g_Bhi[192 * 192];
__device__ float g_Blo[192 * 192];

// ---------------- PTX helpers ----------------
__device__ __forceinline__ float tf32_rnd(float v) {
    uint32_t r;
    asm("cvt.rna.tf32.f32 %0, %1;" : "=r"(r) : "f"(v));
    return __uint_as_float(r);
}
__device__ __forceinline__ void mma_tf32(float* d, const uint32_t* a,
                                         uint32_t b0, uint32_t b1) {
    asm volatile(
        "mma.sync.aligned.m16n8k8.row.col.f32.tf32.tf32.f32 "
        "{%0,%1,%2,%3}, {%4,%5,%6,%7}, {%8,%9}, {%0,%1,%2,%3};"
        : "+f"(d[0]), "+f"(d[1]), "+f"(d[2]), "+f"(d[3])
        : "r"(a[0]), "r"(a[1]), "r"(a[2]), "r"(a[3]), "r"(b0), "r"(b1));
}
__device__ __forceinline__ uint32_t smem_u32(const void* p) {
    uint32_t a;
    asm("{ .reg .u64 t; cvta.to.shared.u64 t, %1; cvt.u32.u64 %0, t; }" : "=r"(a) : "l"(p));
    return a;
}
__device__ __forceinline__ void cpa16(uint32_t dst, const void* src) {
    asm volatile("cp.async.cg.shared.global [%0], [%1], 16;" :: "r"(dst), "l"(src));
}

// ---------------- setup: init + W2 fold (tf32 hi/lo) + bias fold ----------------
__global__ void k_setup(const float* __restrict__ Wz, const float* __restrict__ Wr,
                        const float* __restrict__ Wh, const float* __restrict__ Lz,
                        const float* __restrict__ Lr, const float* __restrict__ Lh,
                        const float* __restrict__ bz, const float* __restrict__ br,
                        const float* __restrict__ bh, const float* __restrict__ bLz,
                        const float* __restrict__ bLr, const float* __restrict__ bLh,
                        int n) {
    int i = blockIdx.x * blockDim.x + threadIdx.x;
    if (i < n) { g_dinv[i] = 1.0f; g_cnt[i] = 0; g_cur[i] = 0; }
    if (i < 192 * 192) {
        int k = i / 192, j = i % 192;   // k: inner dim (A2 cols), j: output col
        float val;
        if (k < 128) {
            int g = j >> 6, jj = j & 63;
            const float* W = (g == 0) ? Wz : ((g == 1) ? Wr : Wh);
            const float* L = (g == 0) ? Lz : ((g == 1) ? Lr : Lh);
            float s = 0.f;
            #pragma unroll 8
            for (int m = 0; m < 64; m++) s = fmaf(W[k * 64 + m], L[m * 64 + jj], s);
            val = s;
        } else {
            int kk = k - 128;
            if (j < 64)       val = Lz[(64 + kk) * 64 + j];
            else if (j < 128) val = Lr[(64 + kk) * 64 + (j - 64)];
            else              val = 0.f;       // (h*R) @ Lh_bot handled in finalize
        }
        float hi = tf32_rnd(val);
        g_Bhi[i] = hi;
        g_Blo[i] = tf32_rnd(val - hi);
    }
    if (i < 192) {
        int g = i >> 6, jj = i & 63;
        const float* b  = (g == 0) ? bz  : ((g == 1) ? br  : bh);
        const float* L  = (g == 0) ? Lz  : ((g == 1) ? Lr  : Lh);
        const float* bL = (g == 0) ? bLz : ((g == 1) ? bLr : bLh);
        float s = bL[jj];
        #pragma unroll 8
        for (int m = 0; m < 64; m++) s = fmaf(b[m], L[m * 64 + jj], s);
        g_c[i] = s;
    }
}

// ---------------- degree histogram ----------------
__global__ void k_hist(const int* __restrict__ ei, const float* __restrict__ ew, int E) {
    int e = blockIdx.x * blockDim.x + threadIdx.x;
    if (e < E) {
        int c = ei[E + e];
        atomicAdd(&g_dinv[c], ew[e]);
        atomicAdd(&g_cnt[c], 1);
    }
}

// ---------------- dinv + exclusive scan, single block ----------------
__global__ void k_scan1(int n, int E) {
    int tid = threadIdx.x;
    for (int i = tid; i < n; i += 1024) g_dinv[i] = rsqrtf(g_dinv[i]);  // deg>=1 (self-loop)

    __shared__ int s[1024];
    int per = (n + 1023) >> 10;
    int start = tid * per;
    int end = start + per; if (end > n) end = n; if (start > n) start = n;
    int sum = 0;
    for (int i = start; i < end; i++) sum += g_cnt[i];
    s[tid] = sum; __syncthreads();
    int v = sum;
    for (int d = 1; d < 1024; d <<= 1) {
        int t = (tid >= d) ? s[tid - d] : 0;
        __syncthreads();
        s[tid] += t;
        __syncthreads();
    }
    int pre = s[tid] - v;
    for (int i = start; i < end; i++) { g_offs[i] = pre; pre += g_cnt[i]; }
    if (tid == 0) g_offs[n] = E;
}

// ---------------- CSR fill ----------------
__global__ void k_fill(const int* __restrict__ ei, const float* __restrict__ ew, int E) {
    int e = blockIdx.x * blockDim.x + threadIdx.x;
    if (e < E) {
        int r = ei[e];
        int c = ei[E + e];
        float nrm = g_dinv[r] * ew[e] * g_dinv[c];
        int pos = g_offs[c] + atomicAdd(&g_cur[c], 1);
        g_edge[pos] = make_int2(r, __float_as_int(nrm));
    }
}

// ---------------- aggregation + h copy, pre-split tf32 hi/lo ----------------
__global__ __launch_bounds__(256) void k_agg(const float* __restrict__ x,
                                             const float* __restrict__ h, int n) {
    int warp = threadIdx.x >> 5, lane = threadIdx.x & 31;
    int node = blockIdx.x * 8 + warp;
    if (node >= n) return;
    const float4* xv = (const float4*)x;
    float di = g_dinv[node];
    float s = di * di;
    float4 a = xv[(size_t)node * 32 + lane];
    float4 acc = make_float4(s * a.x, s * a.y, s * a.z, s * a.w);
    int j = g_offs[node], j1 = g_offs[node + 1];
    for (; j + 1 < j1; j += 2) {
        int2 e0 = g_edge[j], e1 = g_edge[j + 1];
        float4 v0 = xv[(size_t)e0.x * 32 + lane];
        float4 v1 = xv[(size_t)e1.x * 32 + lane];
        float w0 = __int_as_float(e0.y), w1 = __int_as_float(e1.y);
        acc.x = fmaf(w0, v0.x, acc.x); acc.y = fmaf(w0, v0.y, acc.y);
        acc.z = fmaf(w0, v0.z, acc.z); acc.w = fmaf(w0, v0.w, acc.w);
        acc.x = fmaf(w1, v1.x, acc.x); acc.y = fmaf(w1, v1.y, acc.y);
        acc.z = fmaf(w1, v1.z, acc.z); acc.w = fmaf(w1, v1.w, acc.w);
    }
    if (j < j1) {
        int2 e0 = g_edge[j];
        float4 v0 = xv[(size_t)e0.x * 32 + lane];
        float w0 = __int_as_float(e0.y);
        acc.x = fmaf(w0, v0.x, acc.x); acc.y = fmaf(w0, v0.y, acc.y);
        acc.z = fmaf(w0, v0.z, acc.z); acc.w = fmaf(w0, v0.w, acc.w);
    }
    float4 hi, lo;
    hi.x = tf32_rnd(acc.x); lo.x = tf32_rnd(acc.x - hi.x);
    hi.y = tf32_rnd(acc.y); lo.y = tf32_rnd(acc.y - hi.y);
    hi.z = tf32_rnd(acc.z); lo.z = tf32_rnd(acc.z - hi.z);
    hi.w = tf32_rnd(acc.w); lo.w = tf32_rnd(acc.w - hi.w);
    ((float4*)g_Ahi)[(size_t)node * 48 + lane] = hi;
    ((float4*)g_Alo)[(size_t)node * 48 + lane] = lo;
    if (lane < 16) {
        float4 hv = ((const float4*)h)[(size_t)node * 16 + lane];
        float4 hh, hl;
        hh.x = tf32_rnd(hv.x); hl.x = tf32_rnd(hv.x - hh.x);
        hh.y = tf32_rnd(hv.y); hl.y = tf32_rnd(hv.y - hh.y);
        hh.z = tf32_rnd(hv.z); hl.z = tf32_rnd(hv.z - hh.z);
        hh.w = tf32_rnd(hv.w); hl.w = tf32_rnd(hv.w - hh.w);
        ((float4*)g_Ahi)[(size_t)node * 48 + 32 + lane] = hh;
        ((float4*)g_Alo)[(size_t)node * 48 + 32 + lane] = hl;
    }
}

// ---------------- pipelined 3xTF32 mma GEMM: P = A @ W2 ----------------
// CTA 128(M) x 192(N), K=192 in 6 chunks of 32, double-buffered cp.async.
// 8 warps = 2(M) x 4(N); warp tile 64x48 = 4 m-frags x 6 n-frags (m16n8k8).
#define APAD 36
#define BPAD 200
#define F_AHI 0
#define F_ALO 4608
#define F_BHI 9216
#define F_BLO 15616
#define F_BUF 22016
#define SMEM_GEMM_BYTES (2 * F_BUF * 4)

__global__ __launch_bounds__(256) void k_gemm_mma(int n) {
    extern __shared__ float smf[];
    uint32_t sb = smem_u32(smf);
    int tid = threadIdx.x;
    int wid = tid >> 5, lane = tid & 31;
    int warpM = wid >> 2, warpN = wid & 3;
    int gid = lane >> 2, tig = lane & 3;
    int rowBase = blockIdx.x * 128;

    float d[4][6][4];
    #pragma unroll
    for (int mf = 0; mf < 4; mf++)
        #pragma unroll
        for (int nt = 0; nt < 6; nt++)
            #pragma unroll
            for (int q = 0; q < 4; q++) d[mf][nt][q] = 0.f;

    // --- stage chunk 0 ---
    #pragma unroll
    for (int c = 0; c < 1; c++) {
        uint32_t base = sb;
        const float* Ah = g_Ahi + (size_t)rowBase * 192;
        const float* Al = g_Alo + (size_t)rowBase * 192;
        #pragma unroll
        for (int t = 0; t < 4; t++) {
            int idx = tid + t * 256;
            int row = idx >> 3, q = idx & 7;
            cpa16(base + (F_AHI + row * APAD + q * 4) * 4, Ah + (size_t)row * 192 + q * 4);
            cpa16(base + (F_ALO + row * APAD + q * 4) * 4, Al + (size_t)row * 192 + q * 4);
        }
        #pragma unroll
        for (int t = 0; t < 6; t++) {
            int idx = tid + t * 256;
            int k = idx / 48, j4 = idx % 48;
            cpa16(base + (F_BHI + k * BPAD + j4 * 4) * 4, g_Bhi + k * 192 + j4 * 4);
            cpa16(base + (F_BLO + k * BPAD + j4 * 4) * 4, g_Blo + k * 192 + j4 * 4);
        }
        asm volatile("cp.async.commit_group;");
    }

    for (int c = 0; c < 6; c++) {
        if (c + 1 < 6) {   // stage next chunk into other buffer
            uint32_t base = sb + ((c + 1) & 1) * (F_BUF * 4);
            int cc = c + 1;
            const float* Ah = g_Ahi + (size_t)rowBase * 192 + cc * 32;
            const float* Al = g_Alo + (size_t)rowBase * 192 + cc * 32;
            #pragma unroll
            for (int t = 0; t < 4; t++) {
                int idx = tid + t * 256;
                int row = idx >> 3, q = idx & 7;
                cpa16(base + (F_AHI + row * APAD + q * 4) * 4, Ah + (size_t)row * 192 + q * 4);
                cpa16(base + (F_ALO + row * APAD + q * 4) * 4, Al + (size_t)row * 192 + q * 4);
            }
            const float* Bh = g_Bhi + cc * 32 * 192;
            const float* Bl = g_Blo + cc * 32 * 192;
            #pragma unroll
            for (int t = 0; t < 6; t++) {
                int idx = tid + t * 256;
                int k = idx / 48, j4 = idx % 48;
                cpa16(base + (F_BHI + k * BPAD + j4 * 4) * 4, Bh + k * 192 + j4 * 4);
                cpa16(base + (F_BLO + k * BPAD + j4 * 4) * 4, Bl + k * 192 + j4 * 4);
            }
            asm volatile("cp.async.commit_group;");
            asm volatile("cp.async.wait_group 1;");
        } else {
            asm volatile("cp.async.wait_group 0;");
        }
        __syncthreads();

        const uint32_t* bufA_hi = (const uint32_t*)(smf + (c & 1) * F_BUF + F_AHI);
        const uint32_t* bufA_lo = (const uint32_t*)(smf + (c & 1) * F_BUF + F_ALO);
        const uint32_t* bufB_hi = (const uint32_t*)(smf + (c & 1) * F_BUF + F_BHI);
        const uint32_t* bufB_lo = (const uint32_t*)(smf + (c & 1) * F_BUF + F_BLO);

        #pragma unroll
        for (int ks = 0; ks < 4; ks++) {
            uint32_t ahi[4][4], alo[4][4];
            #pragma unroll
            for (int mf = 0; mf < 4; mf++) {
                int r0 = (warpM * 64 + mf * 16 + gid) * APAD + ks * 8 + tig;
                int r1 = r0 + 8 * APAD;
                ahi[mf][0] = bufA_hi[r0];     ahi[mf][1] = bufA_hi[r1];
                ahi[mf][2] = bufA_hi[r0 + 4]; ahi[mf][3] = bufA_hi[r1 + 4];
                alo[mf][0] = bufA_lo[r0];     alo[mf][1] = bufA_lo[r1];
                alo[mf][2] = bufA_lo[r0 + 4]; alo[mf][3] = bufA_lo[r1 + 4];
            }
            #pragma unroll
            for (int nt = 0; nt < 6; nt++) {
                int nn = warpN * 48 + nt * 8 + gid;
                int kb0 = (ks * 8 + tig) * BPAD + nn;
                int kb1 = kb0 + 4 * BPAD;
                uint32_t bh0 = bufB_hi[kb0], bh1 = bufB_hi[kb1];
                uint32_t bl0 = bufB_lo[kb0], bl1 = bufB_lo[kb1];
                #pragma unroll
                for (int mf = 0; mf < 4; mf++) {
                    mma_tf32(d[mf][nt], ahi[mf], bh0, bh1);
                    mma_tf32(d[mf][nt], ahi[mf], bl0, bl1);
                    mma_tf32(d[mf][nt], alo[mf], bh0, bh1);
                }
            }
        }
        __syncthreads();
    }

    // epilogue (g_P padded -> no guards)
    #pragma unroll
    for (int mf = 0; mf < 4; mf++) {
        int row0 = rowBase + warpM * 64 + mf * 16 + gid;
        #pragma unroll
        for (int nt = 0; nt < 6; nt++) {
            int col = warpN * 48 + nt * 8 + tig * 2;
            *(float2*)(g_P + (size_t)row0 * 192 + col) =
                make_float2(d[mf][nt][0], d[mf][nt][1]);
            *(float2*)(g_P + (size_t)(row0 + 8) * 192 + col) =
                make_float2(d[mf][nt][2], d[mf][nt][3]);
        }
    }
}

// ---------------- finalize: gates, (h*R)@Lh_bot, GRU blend, head ----------------
__device__ __forceinline__ float sigf(float v) { return 1.f / (1.f + __expf(-v)); }

__global__ __launch_bounds__(256) void k_final(const float* __restrict__ h,
                                               const float* __restrict__ Lh,
                                               const float* __restrict__ Wo,
                                               const float* __restrict__ bo,
                                               float* __restrict__ out, int n) {
    __shared__ float Lhb[64][65];
    __shared__ float sWo[64];
    __shared__ float sc[192];
    int tid = threadIdx.x;
    for (int i = tid; i < 4096; i += 256) {
        int k = i >> 6, j = i & 63;
        Lhb[k][j] = Lh[(64 + k) * 64 + j];
    }
    if (tid < 64) sWo[tid] = Wo[tid];
    if (tid < 192) sc[tid] = g_c[tid];
    __syncthreads();

    int warp = tid >> 5, lane = tid & 31;
    int node = blockIdx.x * 8 + warp;
    if (node >= n) return;

    const float* p = g_P + (size_t)node * 192;
    float z0 = sigf(p[lane]       + sc[lane]);
    float z1 = sigf(p[lane + 32]  + sc[lane + 32]);
    float r0 = sigf(p[lane + 64]  + sc[lane + 64]);
    float r1 = sigf(p[lane + 96]  + sc[lane + 96]);
    float q0 =      p[lane + 128] + sc[lane + 128];
    float q1 =      p[lane + 160] + sc[lane + 160];

    float h0 = h[(size_t)node * 64 + lane];
    float h1 = h[(size_t)node * 64 + lane + 32];
    float v0 = h0 * r0, v1 = h1 * r1;

    float acc0 = q0, acc1 = q1;
    #pragma unroll
    for (int k = 0; k < 32; k++) {
        float vk = __shfl_sync(0xffffffffu, v0, k);
        acc0 = fmaf(vk, Lhb[k][lane], acc0);
        acc1 = fmaf(vk, Lhb[k][lane + 32], acc1);
    }
    #pragma unroll
    for (int k = 0; k < 32; k++) {
        float vk = __shfl_sync(0xffffffffu, v1, k);
        acc0 = fmaf(vk, Lhb[k + 32][lane], acc0);
        acc1 = fmaf(vk, Lhb[k + 32][lane + 32], acc1);
    }
    float t0 = tanhf(acc0), t1 = tanhf(acc1);
    float hn0 = z0 * h0 + (1.f - z0) * t0;
    float hn1 = z1 * h1 + (1.f - z1) * t1;

    out[n + (size_t)node * 64 + lane]      = hn0;
    out[n + (size_t)node * 64 + lane + 32] = hn1;

    float dot = hn0 * sWo[lane] + hn1 * sWo[lane + 32];
    #pragma unroll
    for (int o = 16; o; o >>= 1) dot += __shfl_down_sync(0xffffffffu, dot, o);
    if (lane == 0) out[node] = dot + bo[0];
}

// ---------------- launcher ----------------
extern "C" void kernel_launch(void* const* d_in, const int* in_sizes, int n_in,
                              void* d_out, int out_size) {
    const float* x   = (const float*)d_in[0];
    const int*   ei  = (const int*)  d_in[1];
    const float* ew  = (const float*)d_in[2];
    const float* h   = (const float*)d_in[3];
    const float* Wz  = (const float*)d_in[4];
    const float* bz  = (const float*)d_in[5];
    const float* Wr  = (const float*)d_in[6];
    const float* br  = (const float*)d_in[7];
    const float* Wh  = (const float*)d_in[8];
    const float* bh  = (const float*)d_in[9];
    const float* Lz  = (const float*)d_in[10];
    const float* bLz = (const float*)d_in[11];
    const float* Lr  = (const float*)d_in[12];
    const float* bLr = (const float*)d_in[13];
    const float* Lh  = (const float*)d_in[14];
    const float* bLh = (const float*)d_in[15];
    const float* Wo  = (const float*)d_in[16];
    const float* bo  = (const float*)d_in[17];
    float* out = (float*)d_out;

    int N = in_sizes[0] / 128;
    int E = in_sizes[2];
    int setup_elems = (N > 192 * 192) ? N : 192 * 192;

    cudaFuncSetAttribute(k_gemm_mma, cudaFuncAttributeMaxDynamicSharedMemorySize,
                         SMEM_GEMM_BYTES);

    k_setup<<<(setup_elems + 255) / 256, 256>>>(Wz, Wr, Wh, Lz, Lr, Lh,
                                                bz, br, bh, bLz, bLr, bLh, N);
    k_hist<<<(E + 255) / 256, 256>>>(ei, ew, E);
    k_scan1<<<1, 1024>>>(N, E);
    k_fill<<<(E + 255) / 256, 256>>>(ei, ew, E);
    k_agg<<<(N + 7) / 8, 256>>>(x, h, N);
    k_gemm_mma<<<(N + 127) / 128, 256, SMEM_GEMM_BYTES>>>(N);
    k_final<<<(N + 7) / 8, 256>>>(h, Lh, Wo, bo, out, N);
}